// round 15
// baseline (speedup 1.0000x reference)
#include <cuda_runtime.h>
#include <cuda_fp16.h>
#include <cstdint>

#define BDIM   2
#define NSEQ   2048
#define DMODEL 1024
#define NHEADS 16
#define DKH    64
#define TD     3072   // 3*DMODEL

// ---------------------------------------------------------------------------
// Scratch (static device globals: allocation-free rule)
// ---------------------------------------------------------------------------
__device__ __half g_qkvhi[(size_t)BDIM * NSEQ * TD];
__device__ __half g_xhi[(size_t)BDIM * NSEQ * DMODEL];
__device__ __half g_xlo[(size_t)BDIM * NSEQ * DMODEL];
__device__ __half g_ctxhi[(size_t)BDIM * NSEQ * DMODEL];
__device__ __half g_wqkvT_h[(size_t)TD * DMODEL];   // [N=3072][K=1024] hi only
__device__ __half g_woutT_h[(size_t)DMODEL * DMODEL];
// unnormalized exp scores, tile-local layout: 512 blocks x 128q x 2048k fp16
__device__ __half g_e[(size_t)512 * 128 * 2048];

// ---------------------------------------------------------------------------
// PTX helpers (baseline ISA only: compiles under compute_103)
// ---------------------------------------------------------------------------
__device__ __forceinline__ uint32_t smem_to_u32(const void* p) {
    uint32_t a;
    asm("{ .reg .u64 t; cvta.to.shared.u64 t, %1; cvt.u32.u64 %0, t; }"
        : "=r"(a) : "l"(p));
    return a;
}
__device__ __forceinline__ void cp16(uint32_t s, const void* g) {
    asm volatile("cp.async.ca.shared.global [%0], [%1], 16;" :: "r"(s), "l"(g));
}
__device__ __forceinline__ void cp_commit() {
    asm volatile("cp.async.commit_group;");
}
template <int N> __device__ __forceinline__ void cp_wait() {
    asm volatile("cp.async.wait_group %0;" :: "n"(N));
}
__device__ __forceinline__ void ldsm_x4(uint32_t* r, uint32_t addr) {
    asm volatile("ldmatrix.sync.aligned.m8n8.x4.shared.b16 {%0,%1,%2,%3}, [%4];"
        : "=r"(r[0]), "=r"(r[1]), "=r"(r[2]), "=r"(r[3]) : "r"(addr));
}
__device__ __forceinline__ void ldsm_x4_t(uint32_t* r, uint32_t addr) {
    asm volatile("ldmatrix.sync.aligned.m8n8.x4.trans.shared.b16 {%0,%1,%2,%3}, [%4];"
        : "=r"(r[0]), "=r"(r[1]), "=r"(r[2]), "=r"(r[3]) : "r"(addr));
}
__device__ __forceinline__ void mma_f16(float* d, const uint32_t* a,
                                        uint32_t b0, uint32_t b1) {
    asm volatile(
        "mma.sync.aligned.m16n8k16.row.col.f32.f16.f16.f32 "
        "{%0,%1,%2,%3}, {%4,%5,%6,%7}, {%8,%9}, {%0,%1,%2,%3};"
        : "+f"(d[0]), "+f"(d[1]), "+f"(d[2]), "+f"(d[3])
        : "r"(a[0]), "r"(a[1]), "r"(a[2]), "r"(a[3]), "r"(b0), "r"(b1));
}
// pack (lo, hi) floats into one f16x2 register (lo -> low half)
__device__ __forceinline__ uint32_t pack_h2(float lo, float hi) {
    uint32_t p;
    asm("cvt.rn.f16x2.f32 %0, %1, %2;" : "=r"(p) : "f"(hi), "f"(lo));
    return p;
}
// vectorized exp2: returns f16x2{exp2(lo), exp2(hi)}
__device__ __forceinline__ uint32_t ex2_h2(float lo, float hi) {
    uint32_t p, r;
    asm("cvt.rn.f16x2.f32 %0, %1, %2;" : "=r"(p) : "f"(hi), "f"(lo));
    asm("ex2.approx.f16x2 %0, %1;" : "=r"(r) : "r"(p));
    return r;
}
__device__ __forceinline__ void pack_hl(float x, float y,
                                        uint32_t& hp, uint32_t& lp) {
    __half2 hh = __floats2half2_rn(x, y);
    __half2 ll = __floats2half2_rn(x - __half2float(__low2half(hh)),
                                   y - __half2float(__high2half(hh)));
    hp = *(uint32_t*)&hh; lp = *(uint32_t*)&ll;
}
__device__ __forceinline__ void split_store2(__half* hi, __half* lo,
                                             size_t idx, float x, float y) {
    uint32_t hp, lp;
    pack_hl(x, y, hp, lp);
    *(uint32_t*)(hi + idx) = hp;
    *(uint32_t*)(lo + idx) = lp;
}

// ---------------------------------------------------------------------------
// Split fp32 -> (hi, lo) fp16, elementwise
// ---------------------------------------------------------------------------
__global__ __launch_bounds__(256) void split_kernel(
    const float* __restrict__ src, __half* __restrict__ hi,
    __half* __restrict__ lo, int n2)
{
    for (int i = blockIdx.x * blockDim.x + threadIdx.x; i < n2;
         i += gridDim.x * blockDim.x) {
        float2 v = ((const float2*)src)[i];
        split_store2(hi, lo, (size_t)i * 2, v.x, v.y);
    }
}

// ---------------------------------------------------------------------------
// Transpose + fp16 cast: src [K][N] fp32 -> hiT [N][K] fp16 (hi only)
// ---------------------------------------------------------------------------
__global__ __launch_bounds__(256) void transpose_h_kernel(
    const float* __restrict__ src, __half* __restrict__ hiT, int K, int N)
{
    __shared__ float tile[32][33];
    const int tx = threadIdx.x, ty = threadIdx.y;   // (32, 8)
    const int n0 = blockIdx.x * 32, k0 = blockIdx.y * 32;

    #pragma unroll
    for (int i = 0; i < 4; ++i)
        tile[ty + i * 8][tx] = src[(size_t)(k0 + ty + i * 8) * N + n0 + tx];
    __syncthreads();

    #pragma unroll
    for (int i = 0; i < 4; ++i) {
        int n = n0 + ty + i * 8;
        hiT[(size_t)n * K + k0 + tx] = __float2half_rn(tile[tx][ty + i * 8]);
    }
}

// ---------------------------------------------------------------------------
// fp16 split GEMM (R11-proven double-sync 2-stage), HASLO template.
// C = A @ B + bias; A = hi (+lo) fp16 [M][K]; B = hi fp16 [Nc][K].
// fp16-hi output path pre-scales Q columns (col%192 < 64) by 0.125*log2(e).
// ---------------------------------------------------------------------------
#define AHI_OFF 0
#define ALO_OFF 10240
#define BHI_OFF 20480
#define STAGE_SZ 30720
static constexpr size_t GEMM_SMEM = 2 * STAGE_SZ;  // 61440

template <bool HASLO>
__global__ __launch_bounds__(256, 2) void gemm_mma_kernel(
    const __half* __restrict__ Ahi, const __half* __restrict__ Alo,
    const __half* __restrict__ BTh,
    const float* __restrict__ bias, float* __restrict__ C,
    __half* __restrict__ Chi,
    int M, int Nc, int K)
{
    extern __shared__ char smc[];
    const uint32_t sbase = smem_to_u32(smc);
    const int tid = threadIdx.x;
    const int lane = tid & 31, wid = tid >> 5;
    const int wm = (wid & 3) * 32;
    const int wn = (wid >> 2) * 64;
    const int bm = blockIdx.y * 128, bn = blockIdx.x * 128;

    const int lrow = tid >> 1;
    const int lc   = (tid & 1) * 2;

    const __half* gAh = Ahi + (size_t)(bm + lrow) * K + lc * 8;
    const __half* gAl = HASLO ? Alo + (size_t)(bm + lrow) * K + lc * 8 : nullptr;
    const __half* gBh = BTh + (size_t)(bn + lrow) * K + lc * 8;

    const uint32_t sRow = lrow * 80 + lc * 16;

    auto load_stage = [&](int k0, int buf) {
        uint32_t st = sbase + buf * STAGE_SZ;
        cp16(st + AHI_OFF + sRow,      gAh + k0);
        cp16(st + AHI_OFF + sRow + 16, gAh + k0 + 8);
        if (HASLO) {
            cp16(st + ALO_OFF + sRow,      gAl + k0);
            cp16(st + ALO_OFF + sRow + 16, gAl + k0 + 8);
        }
        cp16(st + BHI_OFF + sRow,      gBh + k0);
        cp16(st + BHI_OFF + sRow + 16, gBh + k0 + 8);
    };

    float acc[2][8][4];
    #pragma unroll
    for (int a = 0; a < 2; ++a)
        #pragma unroll
        for (int b = 0; b < 8; ++b)
            #pragma unroll
            for (int c = 0; c < 4; ++c) acc[a][b][c] = 0.f;

    const int arow = wm + (lane & 15);
    const int brow = wn + (lane & 15);
    const int klb  = (lane >> 4) * 16;

    const int nit = K / 32;
    load_stage(0, 0);
    cp_commit();

    for (int i = 0; i < nit; ++i) {
        const int cur = i & 1;
        if (i + 1 < nit) { load_stage((i + 1) * 32, cur ^ 1); cp_commit(); }
        if (i + 1 < nit) cp_wait<1>(); else cp_wait<0>();
        __syncthreads();

        const uint32_t st = sbase + cur * STAGE_SZ;
        #pragma unroll
        for (int ks = 0; ks < 2; ++ks) {
            const uint32_t kb = ks * 32 + klb;
            uint32_t ah[2][4], al[2][4], bh[4][4];
            #pragma unroll
            for (int mt = 0; mt < 2; ++mt) {
                ldsm_x4(ah[mt], st + AHI_OFF + (arow + mt * 16) * 80 + kb);
                if (HASLO)
                    ldsm_x4(al[mt], st + ALO_OFF + (arow + mt * 16) * 80 + kb);
            }
            #pragma unroll
            for (int nt = 0; nt < 4; ++nt)
                ldsm_x4(bh[nt], st + BHI_OFF + (brow + nt * 16) * 80 + kb);

            #pragma unroll
            for (int mt = 0; mt < 2; ++mt)
                #pragma unroll
                for (int j = 0; j < 8; ++j)
                    mma_f16(acc[mt][j], ah[mt], bh[j >> 1][j & 1],
                            bh[j >> 1][(j & 1) + 2]);
            if (HASLO) {
                #pragma unroll
                for (int mt = 0; mt < 2; ++mt)
                    #pragma unroll
                    for (int j = 0; j < 8; ++j)
                        mma_f16(acc[mt][j], al[mt], bh[j >> 1][j & 1],
                                bh[j >> 1][(j & 1) + 2]);
            }
        }
        __syncthreads();
    }

    // epilogue
    const int g = lane >> 2, tq = lane & 3;
    #pragma unroll
    for (int mt = 0; mt < 2; ++mt) {
        const int r0 = bm + wm + mt * 16 + g;
        #pragma unroll
        for (int j = 0; j < 8; ++j) {
            const int col = bn + wn + j * 8 + tq * 2;
            const float b0 = bias[col], b1 = bias[col + 1];
            float v00 = acc[mt][j][0] + b0, v01 = acc[mt][j][1] + b1;
            float v10 = acc[mt][j][2] + b0, v11 = acc[mt][j][3] + b1;
            if (C) {
                *(float2*)&C[(size_t)r0 * Nc + col] = make_float2(v00, v01);
                *(float2*)&C[(size_t)(r0 + 8) * Nc + col] = make_float2(v10, v11);
            } else {
                // QKV path: pre-scale Q columns by 0.125*log2(e)
                const float s = ((col % 192) < 64) ? 0.18033688f : 1.0f;
                *(uint32_t*)(Chi + (size_t)r0 * Nc + col) =
                    pack_h2(v00 * s, v01 * s);
                *(uint32_t*)(Chi + (size_t)(r0 + 8) * Nc + col) =
                    pack_h2(v10 * s, v11 * s);
            }
        }
    }
}

// ---------------------------------------------------------------------------
// MMA attention (Q pre-scaled: S already in log2 units):
// Pass 1: S = QK (hi), e = ex2.f16x2(S) as PV a-fragments, l via ones-mma,
//         ctxU += e*V; e stored to g_e in tile-local coalesced layout
//         eb[kt][kc][tid] = uint4{aph0..3}, AFTER the mmas of each kc.
// Pass 2: streaming weighted column-sum of stored e (no mma, no exp).
// Epilogue: ctx = ctxU / l, hi-only fp16 store.
// ---------------------------------------------------------------------------
#define ATT_QHI   0
#define ATT_STG   18432
#define ATT_STAGE 18432
#define ATT_VOF   9216
#define ATT_SMEM  55296

__global__ __launch_bounds__(256, 2) void attn_mma_kernel(float* __restrict__ attn_mean)
{
    extern __shared__ char smc[];
    const uint32_t sb = smem_to_u32(smc);
    const int tid = threadIdx.x, lane = tid & 31, wid = tid >> 5;
    const int g = lane >> 2, tg = lane & 3;
    const int h = blockIdx.y >> 1, b = blockIdx.y & 1;
    const int q0 = blockIdx.x * 128;
    const float MSCALE = 1.0f / (NHEADS * (float)NSEQ);
    const uint32_t ONESH2 = 0x3C003C00u;   // f16x2 {1.0, 1.0}

    __half* eb = g_e + (size_t)(blockIdx.y * 16 + blockIdx.x) * (128 * 2048);

    const int lr = tid >> 3, lch = tid & 7;
    const size_t rowQ  = ((size_t)(b * NSEQ + q0 + lr)) * TD + h * 192 + lch * 8;
    const size_t rowKV = ((size_t)(b * NSEQ + lr)) * TD + h * 192 + lch * 8;
    const uint32_t soff = lr * 144 + lch * 16;
    const size_t KTSTEP = (size_t)64 * TD;

    auto loadQ = [&]() {
        #pragma unroll
        for (int i = 0; i < 4; ++i)
            cp16(sb + ATT_QHI + soff + i * 32 * 144,
                 g_qkvhi + rowQ + (size_t)i * 32 * TD);
    };
    auto loadKV = [&](int kt, int s) {
        uint32_t st = sb + ATT_STG + s * ATT_STAGE;
        size_t base = rowKV + (size_t)kt * KTSTEP + 64;
        cp16(st + soff,            g_qkvhi + base);
        cp16(st + soff + 32 * 144, g_qkvhi + base + 32 * TD);
        cp16(st + ATT_VOF + soff,            g_qkvhi + base + 64);
        cp16(st + ATT_VOF + soff + 32 * 144, g_qkvhi + base + 64 + 32 * TD);
    };

    const uint32_t klb  = (lane >> 4) * 16;
    const uint32_t arow = wid * 16 + (lane & 15);
    const uint32_t brow = lane & 15;

    auto computeS = [&](uint32_t stg, float (*acc)[4]) {
        #pragma unroll
        for (int ks = 0; ks < 4; ++ks) {
            const uint32_t kb = ks * 32 + klb;
            uint32_t ah[4], bh[4][4];
            ldsm_x4(ah, sb + ATT_QHI + arow * 144 + kb);
            #pragma unroll
            for (int nt = 0; nt < 4; ++nt)
                ldsm_x4(bh[nt], stg + (brow + nt * 16) * 144 + kb);
            #pragma unroll
            for (int nt = 0; nt < 4; ++nt)
                #pragma unroll
                for (int o = 0; o < 2; ++o)
                    mma_f16(acc[nt * 2 + o], ah, bh[nt][o], bh[nt][o + 2]);
        }
    };

    float lacc[4] = {0.f, 0.f, 0.f, 0.f};
    float ctx[8][4];
    #pragma unroll
    for (int j = 0; j < 8; ++j)
        #pragma unroll
        for (int x = 0; x < 4; ++x) ctx[j][x] = 0.f;

    const int er0 = wid * 16 + g;          // e output rows er0, er0+8
    // e store base for this thread (halves): layout [kt][kc][tid] x uint4
    __half* ebt = eb + (size_t)tid * 8;

    // ====== PASS 1: e = ex2(S) f16x2, l via ones-mma, ctxU += e*V,
    //                e stored (coalesced, after mmas) =====================
    loadQ(); loadKV(0, 0); cp_commit();
    loadKV(1, 1); cp_commit();

    for (int kt = 0; kt < 32; ++kt) {
        cp_wait<1>();
        __syncthreads();
        const uint32_t stg = sb + ATT_STG + (kt & 1) * ATT_STAGE;

        float acc[8][4];
        #pragma unroll
        for (int j = 0; j < 8; ++j)
            #pragma unroll
            for (int x = 0; x < 4; ++x) acc[j][x] = 0.f;
        computeS(stg, acc);

        #pragma unroll
        for (int kc = 0; kc < 4; ++kc) {
            const int j0 = kc * 2, j1 = j0 + 1;
            uint32_t aph[4];
            aph[0] = ex2_h2(acc[j0][0], acc[j0][1]);   // q=er0,   k=kc*16+tg*2
            aph[1] = ex2_h2(acc[j0][2], acc[j0][3]);   // q=er0+8, same k
            aph[2] = ex2_h2(acc[j1][0], acc[j1][1]);   // q=er0,   k=+8
            aph[3] = ex2_h2(acc[j1][2], acc[j1][3]);   // q=er0+8, k=+8

            mma_f16(lacc, aph, ONESH2, ONESH2);   // l += row sums of e

            #pragma unroll
            for (int dkt = 0; dkt < 4; ++dkt) {
                const uint32_t off = (kc * 16 + (lane & 15)) * 144 + dkt * 32
                                   + (lane >> 4) * 16;
                uint32_t vh[4];
                ldsm_x4_t(vh, stg + ATT_VOF + off);
                mma_f16(ctx[dkt * 2],     aph, vh[0], vh[1]);
                mma_f16(ctx[dkt * 2 + 1], aph, vh[2], vh[3]);
            }

            // coalesced e store: one uint4 per thread per kc
            uint4 ev = make_uint4(aph[0], aph[1], aph[2], aph[3]);
            *(uint4*)(ebt + (size_t)(kt * 4 + kc) * 2048) = ev;
        }

        __syncthreads();
        if (kt + 2 < 32) loadKV(kt + 2, kt & 1);
        cp_commit();
    }

    // all columns of the l-mma are identical: no reduction needed
    const float l0 = lacc[0], l1 = lacc[2];
    const float rinv0 = 1.0f / l0, rinv1 = 1.0f / l1;

    // publish rinv per query row to smem (stage area is dead now)
    float* s_rinv = (float*)(smc + ATT_STG);
    if (tg == 0) {
        s_rinv[er0]     = rinv0;
        s_rinv[er0 + 8] = rinv1;
    }
    __syncthreads();   // also publishes this CTA's g_e writes (same-CTA scope)

    // ====== PASS 2: streaming weighted column sums ========================
    {
        const int pkt = tid >> 3;           // 0..31
        const int sub = tid & 7;
        const int pkc = sub >> 1;           // 0..3
        const int khalf = sub & 1;          // 0/1 (k +0 or +8)
        // values for this (kt,kc): uint4 per src thread; we need the
        // uint32 pair (khalf*2 + qhalf) of every src thread.
        const uint32_t* ebase = (const uint32_t*)(eb
            + (size_t)(pkt * 4 + pkc) * 2048 * 8 / 8 * 8);  // halves
        const uint32_t* ev = (const uint32_t*)(eb) +
            (size_t)(pkt * 4 + pkc) * 1024;   // 256 src * 4 uint32
        (void)ebase;

        float sum[8] = {0.f, 0.f, 0.f, 0.f, 0.f, 0.f, 0.f, 0.f};
        #pragma unroll 2
        for (int src = 0; src < 256; ++src) {
            const int swid = src >> 5, sg = (src >> 2) & 7, stg2 = src & 3;
            // load both q-halves for this (src, khalf): 2 consecutive uint32
            const uint32_t* p = ev + src * 4 + khalf * 2;
            uint32_t e0 = p[0];   // qhalf 0: q = swid*16+sg
            uint32_t e1 = p[1];   // qhalf 1: q = swid*16+sg+8
            const float r0 = s_rinv[swid * 16 + sg];
            const float r1 = s_rinv[swid * 16 + sg + 8];
            float2 f0 = __half22float2(*(__half2*)&e0);
            float2 f1 = __half22float2(*(__half2*)&e1);
            sum[stg2 * 2 + 0] += f0.x * r0 + f1.x * r1;
            sum[stg2 * 2 + 1] += f0.y * r0 + f1.y * r1;
        }
        const int kbase = pkt * 64 + pkc * 16 + khalf * 8;
        float* am = &attn_mean[b * NSEQ + kbase];
        #pragma unroll
        for (int t = 0; t < 8; ++t)
            atomicAdd(&am[t], sum[t] * MSCALE);
    }

    // epilogue: normalize ctx, hi-only fp16 store (B, N, H*dk layout)
    const int r0 = q0 + er0;
    #pragma unroll
    for (int nd = 0; nd < 8; ++nd) {
        const int col = h * 64 + nd * 8 + tg * 2;
        size_t i0 = ((size_t)(b * NSEQ + r0)) * DMODEL + col;
        *(uint32_t*)(g_ctxhi + i0) =
            pack_h2(ctx[nd][0] * rinv0, ctx[nd][1] * rinv0);
        *(uint32_t*)(g_ctxhi + i0 + 8 * DMODEL) =
            pack_h2(ctx[nd][2] * rinv1, ctx[nd][3] * rinv1);
    }
}

// ---------------------------------------------------------------------------
extern "C" void kernel_launch(void* const* d_in, const int* in_sizes, int n_in,
                              void* d_out, int out_size)
{
    const float* x     = (const float*)d_in[0];
    const float* w_qkv = (const float*)d_in[1];
    const float* b_qkv = (const float*)d_in[2];
    const float* w_out = (const float*)d_in[3];
    const float* b_out = (const float*)d_in[4];
    float* out = (float*)d_out;

    __half *qh, *xhi, *xlo, *ctxhi, *wqh, *woh;
    cudaGetSymbolAddress((void**)&qh, g_qkvhi);
    cudaGetSymbolAddress((void**)&xhi, g_xhi);
    cudaGetSymbolAddress((void**)&xlo, g_xlo);
    cudaGetSymbolAddress((void**)&ctxhi, g_ctxhi);
    cudaGetSymbolAddress((void**)&wqh, g_wqkvT_h);
    cudaGetSymbolAddress((void**)&woh, g_woutT_h);

    const int M = BDIM * NSEQ;                    // 4096
    float* attn_mean = out + (size_t)M * DMODEL;  // second output region

    cudaMemsetAsync(attn_mean, 0, (size_t)BDIM * NSEQ * sizeof(float));

    // prep: split input, cast+transpose weights (hi only)
    split_kernel<<<1024, 256>>>(x, xhi, xlo, M * DMODEL / 2);
    transpose_h_kernel<<<dim3(TD / 32, DMODEL / 32), dim3(32, 8)>>>(
        w_qkv, wqh, DMODEL, TD);
    transpose_h_kernel<<<dim3(DMODEL / 32, DMODEL / 32), dim3(32, 8)>>>(
        w_out, woh, DMODEL, DMODEL);

    cudaFuncSetAttribute(gemm_mma_kernel<true>,
                         cudaFuncAttributeMaxDynamicSharedMemorySize,
                         (int)GEMM_SMEM);
    cudaFuncSetAttribute(gemm_mma_kernel<false>,
                         cudaFuncAttributeMaxDynamicSharedMemorySize,
                         (int)GEMM_SMEM);
    cudaFuncSetAttribute(attn_mma_kernel,
                         cudaFuncAttributeMaxDynamicSharedMemorySize,
                         ATT_SMEM);

    // QKV projection (A split hi/lo) -> fp16 hi-only output, Q pre-scaled
    gemm_mma_kernel<true><<<dim3(TD / 128, M / 128), 256, GEMM_SMEM>>>(
        xhi, xlo, wqh, b_qkv, nullptr, qh, M, TD, DMODEL);

    // attention (single-compute + streaming colsum pass)
    attn_mma_kernel<<<dim3(NSEQ / 128, NHEADS * BDIM), 256, ATT_SMEM>>>(attn_mean);

    // output projection (A hi only) -> fp32 final output
    gemm_mma_kernel<false><<<dim3(DMODEL / 128, M / 128), 256, GEMM_SMEM>>>(
        ctxhi, nullptr, woh, b_out, out, nullptr, M, DMODEL, DMODEL);
}

// round 16
// speedup vs baseline: 1.3483x; 1.3483x over previous
#include <cuda_runtime.h>
#include <cuda_fp16.h>
#include <cstdint>

#define BDIM   2
#define NSEQ   2048
#define DMODEL 1024
#define NHEADS 16
#define DKH    64
#define TD     3072   // 3*DMODEL

// ---------------------------------------------------------------------------
// Scratch (static device globals: allocation-free rule)
// ---------------------------------------------------------------------------
__device__ __half g_qkvhi[(size_t)BDIM * NSEQ * TD];
__device__ __half g_xhi[(size_t)BDIM * NSEQ * DMODEL];
__device__ __half g_ctxhi[(size_t)BDIM * NSEQ * DMODEL];
__device__ __half g_wqkvT_h[(size_t)TD * DMODEL];   // [N=3072][K=1024]
__device__ __half g_woutT_h[(size_t)DMODEL * DMODEL];

// ---------------------------------------------------------------------------
// PTX helpers (baseline ISA only: compiles under compute_103)
// ---------------------------------------------------------------------------
__device__ __forceinline__ uint32_t smem_to_u32(const void* p) {
    uint32_t a;
    asm("{ .reg .u64 t; cvta.to.shared.u64 t, %1; cvt.u32.u64 %0, t; }"
        : "=r"(a) : "l"(p));
    return a;
}
__device__ __forceinline__ void cp16(uint32_t s, const void* g) {
    asm volatile("cp.async.ca.shared.global [%0], [%1], 16;" :: "r"(s), "l"(g));
}
__device__ __forceinline__ void cp_commit() {
    asm volatile("cp.async.commit_group;");
}
template <int N> __device__ __forceinline__ void cp_wait() {
    asm volatile("cp.async.wait_group %0;" :: "n"(N));
}
__device__ __forceinline__ void ldsm_x4(uint32_t* r, uint32_t addr) {
    asm volatile("ldmatrix.sync.aligned.m8n8.x4.shared.b16 {%0,%1,%2,%3}, [%4];"
        : "=r"(r[0]), "=r"(r[1]), "=r"(r[2]), "=r"(r[3]) : "r"(addr));
}
__device__ __forceinline__ void ldsm_x4_t(uint32_t* r, uint32_t addr) {
    asm volatile("ldmatrix.sync.aligned.m8n8.x4.trans.shared.b16 {%0,%1,%2,%3}, [%4];"
        : "=r"(r[0]), "=r"(r[1]), "=r"(r[2]), "=r"(r[3]) : "r"(addr));
}
__device__ __forceinline__ void mma_f16(float* d, const uint32_t* a,
                                        uint32_t b0, uint32_t b1) {
    asm volatile(
        "mma.sync.aligned.m16n8k16.row.col.f32.f16.f16.f32 "
        "{%0,%1,%2,%3}, {%4,%5,%6,%7}, {%8,%9}, {%0,%1,%2,%3};"
        : "+f"(d[0]), "+f"(d[1]), "+f"(d[2]), "+f"(d[3])
        : "r"(a[0]), "r"(a[1]), "r"(a[2]), "r"(a[3]), "r"(b0), "r"(b1));
}
__device__ __forceinline__ float lg2(float x) {
    float y; asm("lg2.approx.f32 %0, %1;" : "=f"(y) : "f"(x)); return y;
}
// pack (lo, hi) floats into one f16x2 register (lo -> low half)
__device__ __forceinline__ uint32_t pack_h2(float lo, float hi) {
    uint32_t p;
    asm("cvt.rn.f16x2.f32 %0, %1, %2;" : "=r"(p) : "f"(hi), "f"(lo));
    return p;
}
// vectorized exp2: returns f16x2{exp2(lo), exp2(hi)}
__device__ __forceinline__ uint32_t ex2_h2(float lo, float hi) {
    uint32_t p, r;
    asm("cvt.rn.f16x2.f32 %0, %1, %2;" : "=r"(p) : "f"(hi), "f"(lo));
    asm("ex2.approx.f16x2 %0, %1;" : "=r"(r) : "r"(p));
    return r;
}

// ---------------------------------------------------------------------------
// Cast fp32 -> fp16, elementwise (vectorized)
// ---------------------------------------------------------------------------
__global__ __launch_bounds__(256) void cast_h_kernel(
    const float* __restrict__ src, __half* __restrict__ dst, int n4)
{
    for (int i = blockIdx.x * blockDim.x + threadIdx.x; i < n4;
         i += gridDim.x * blockDim.x) {
        float4 v = ((const float4*)src)[i];
        uint2 o;
        o.x = pack_h2(v.x, v.y);
        o.y = pack_h2(v.z, v.w);
        ((uint2*)dst)[i] = o;
    }
}

// ---------------------------------------------------------------------------
// Transpose + fp16 cast: src [K][N] fp32 -> hiT [N][K] fp16
// ---------------------------------------------------------------------------
__global__ __launch_bounds__(256) void transpose_h_kernel(
    const float* __restrict__ src, __half* __restrict__ hiT, int K, int N)
{
    __shared__ float tile[32][33];
    const int tx = threadIdx.x, ty = threadIdx.y;   // (32, 8)
    const int n0 = blockIdx.x * 32, k0 = blockIdx.y * 32;

    #pragma unroll
    for (int i = 0; i < 4; ++i)
        tile[ty + i * 8][tx] = src[(size_t)(k0 + ty + i * 8) * N + n0 + tx];
    __syncthreads();

    #pragma unroll
    for (int i = 0; i < 4; ++i) {
        int n = n0 + ty + i * 8;
        hiT[(size_t)n * K + k0 + tx] = __float2half_rn(tile[tx][ty + i * 8]);
    }
}

// ---------------------------------------------------------------------------
// fp16 hi-only GEMM (R11-proven double-sync 2-stage pipeline):
// C = A @ B + bias; A = fp16 [M][K]; B = fp16 transposed [Nc][K].
// Output: fp32 C, or fp16 Chi with Q pre-scale (col%192 < 64 by 0.125*log2e).
// CTA 128x128, BK=32, 256 threads, warp tile 32x64.
// ---------------------------------------------------------------------------
#define AHI_OFF 0
#define BHI_OFF 10240
#define STAGE_SZ 20480
static constexpr size_t GEMM_SMEM = 2 * STAGE_SZ;  // 40960

__global__ __launch_bounds__(256, 2) void gemm_mma_kernel(
    const __half* __restrict__ Ahi, const __half* __restrict__ BTh,
    const float* __restrict__ bias, float* __restrict__ C,
    __half* __restrict__ Chi,
    int M, int Nc, int K)
{
    extern __shared__ char smc[];
    const uint32_t sbase = smem_to_u32(smc);
    const int tid = threadIdx.x;
    const int lane = tid & 31, wid = tid >> 5;
    const int wm = (wid & 3) * 32;
    const int wn = (wid >> 2) * 64;
    const int bm = blockIdx.y * 128, bn = blockIdx.x * 128;

    const int lrow = tid >> 1;
    const int lc   = (tid & 1) * 2;

    const __half* gAh = Ahi + (size_t)(bm + lrow) * K + lc * 8;
    const __half* gBh = BTh + (size_t)(bn + lrow) * K + lc * 8;

    const uint32_t sRow = lrow * 80 + lc * 16;

    auto load_stage = [&](int k0, int buf) {
        uint32_t st = sbase + buf * STAGE_SZ;
        cp16(st + AHI_OFF + sRow,      gAh + k0);
        cp16(st + AHI_OFF + sRow + 16, gAh + k0 + 8);
        cp16(st + BHI_OFF + sRow,      gBh + k0);
        cp16(st + BHI_OFF + sRow + 16, gBh + k0 + 8);
    };

    float acc[2][8][4];
    #pragma unroll
    for (int a = 0; a < 2; ++a)
        #pragma unroll
        for (int b = 0; b < 8; ++b)
            #pragma unroll
            for (int c = 0; c < 4; ++c) acc[a][b][c] = 0.f;

    const int arow = wm + (lane & 15);
    const int brow = wn + (lane & 15);
    const int klb  = (lane >> 4) * 16;

    const int nit = K / 32;
    load_stage(0, 0);
    cp_commit();

    for (int i = 0; i < nit; ++i) {
        const int cur = i & 1;
        if (i + 1 < nit) { load_stage((i + 1) * 32, cur ^ 1); cp_commit(); }
        if (i + 1 < nit) cp_wait<1>(); else cp_wait<0>();
        __syncthreads();

        const uint32_t st = sbase + cur * STAGE_SZ;
        #pragma unroll
        for (int ks = 0; ks < 2; ++ks) {
            const uint32_t kb = ks * 32 + klb;
            uint32_t ah[2][4], bh[4][4];
            #pragma unroll
            for (int mt = 0; mt < 2; ++mt)
                ldsm_x4(ah[mt], st + AHI_OFF + (arow + mt * 16) * 80 + kb);
            #pragma unroll
            for (int nt = 0; nt < 4; ++nt)
                ldsm_x4(bh[nt], st + BHI_OFF + (brow + nt * 16) * 80 + kb);

            #pragma unroll
            for (int mt = 0; mt < 2; ++mt)
                #pragma unroll
                for (int j = 0; j < 8; ++j)
                    mma_f16(acc[mt][j], ah[mt], bh[j >> 1][j & 1],
                            bh[j >> 1][(j & 1) + 2]);
        }
        __syncthreads();
    }

    // epilogue
    const int g = lane >> 2, tq = lane & 3;
    #pragma unroll
    for (int mt = 0; mt < 2; ++mt) {
        const int r0 = bm + wm + mt * 16 + g;
        #pragma unroll
        for (int j = 0; j < 8; ++j) {
            const int col = bn + wn + j * 8 + tq * 2;
            const float b0 = bias[col], b1 = bias[col + 1];
            float v00 = acc[mt][j][0] + b0, v01 = acc[mt][j][1] + b1;
            float v10 = acc[mt][j][2] + b0, v11 = acc[mt][j][3] + b1;
            if (C) {
                *(float2*)&C[(size_t)r0 * Nc + col] = make_float2(v00, v01);
                *(float2*)&C[(size_t)(r0 + 8) * Nc + col] = make_float2(v10, v11);
            } else {
                // QKV path: pre-scale Q columns by 0.125*log2(e)
                const float s = ((col % 192) < 64) ? 0.18033688f : 1.0f;
                *(uint32_t*)(Chi + (size_t)r0 * Nc + col) =
                    pack_h2(v00 * s, v01 * s);
                *(uint32_t*)(Chi + (size_t)(r0 + 8) * Nc + col) =
                    pack_h2(v10 * s, v11 * s);
            }
        }
    }
}

// ---------------------------------------------------------------------------
// MMA attention (R13-proven; Q pre-scaled so S is in log2 units):
// Pass 1: S = QK (hi), e = ex2.f16x2(S) directly as PV a-fragments,
//         l via ones-column mma, ctxU += e*V.
// Pass 2: recompute S (hi), f16x2 exp with final normalizer, colsum atomics.
// Epilogue: ctx = ctxU / l, hi-only fp16 store.
// ---------------------------------------------------------------------------
#define ATT_QHI   0
#define ATT_STG   18432
#define ATT_STAGE 18432
#define ATT_VOF   9216
#define ATT_SMEM  55296

__global__ __launch_bounds__(256, 2) void attn_mma_kernel(float* __restrict__ attn_mean)
{
    extern __shared__ char smc[];
    const uint32_t sb = smem_to_u32(smc);
    const int tid = threadIdx.x, lane = tid & 31, wid = tid >> 5;
    const int g = lane >> 2, tg = lane & 3;
    const int h = blockIdx.y >> 1, b = blockIdx.y & 1;
    const int q0 = blockIdx.x * 128;
    const float MSCALE = 1.0f / (NHEADS * (float)NSEQ);
    const uint32_t ONESH2 = 0x3C003C00u;   // f16x2 {1.0, 1.0}

    const int lr = tid >> 3, lch = tid & 7;
    const size_t rowQ  = ((size_t)(b * NSEQ + q0 + lr)) * TD + h * 192 + lch * 8;
    const size_t rowKV = ((size_t)(b * NSEQ + lr)) * TD + h * 192 + lch * 8;
    const uint32_t soff = lr * 144 + lch * 16;
    const size_t KTSTEP = (size_t)64 * TD;

    auto loadQ = [&]() {
        #pragma unroll
        for (int i = 0; i < 4; ++i)
            cp16(sb + ATT_QHI + soff + i * 32 * 144,
                 g_qkvhi + rowQ + (size_t)i * 32 * TD);
    };
    auto loadK = [&](int kt, int s) {
        uint32_t st = sb + ATT_STG + s * ATT_STAGE;
        size_t base = rowKV + (size_t)kt * KTSTEP + 64;
        cp16(st + soff,            g_qkvhi + base);
        cp16(st + soff + 32 * 144, g_qkvhi + base + 32 * TD);
    };
    auto loadKV = [&](int kt, int s) {
        uint32_t st = sb + ATT_STG + s * ATT_STAGE;
        size_t base = rowKV + (size_t)kt * KTSTEP + 64;
        cp16(st + soff,            g_qkvhi + base);
        cp16(st + soff + 32 * 144, g_qkvhi + base + 32 * TD);
        cp16(st + ATT_VOF + soff,            g_qkvhi + base + 64);
        cp16(st + ATT_VOF + soff + 32 * 144, g_qkvhi + base + 64 + 32 * TD);
    };

    const uint32_t klb  = (lane >> 4) * 16;
    const uint32_t arow = wid * 16 + (lane & 15);
    const uint32_t brow = lane & 15;

    auto computeS = [&](uint32_t stg, float (*acc)[4]) {
        #pragma unroll
        for (int ks = 0; ks < 4; ++ks) {
            const uint32_t kb = ks * 32 + klb;
            uint32_t ah[4], bh[4][4];
            ldsm_x4(ah, sb + ATT_QHI + arow * 144 + kb);
            #pragma unroll
            for (int nt = 0; nt < 4; ++nt)
                ldsm_x4(bh[nt], stg + (brow + nt * 16) * 144 + kb);
            #pragma unroll
            for (int nt = 0; nt < 4; ++nt)
                #pragma unroll
                for (int o = 0; o < 2; ++o)
                    mma_f16(acc[nt * 2 + o], ah, bh[nt][o], bh[nt][o + 2]);
        }
    };

    float lacc[4] = {0.f, 0.f, 0.f, 0.f};
    float ctx[8][4];
    #pragma unroll
    for (int j = 0; j < 8; ++j)
        #pragma unroll
        for (int x = 0; x < 4; ++x) ctx[j][x] = 0.f;

    // ====== PASS 1: e = ex2(S) f16x2, l via ones-mma, ctxU += e*V =========
    loadQ(); loadKV(0, 0); cp_commit();
    loadKV(1, 1); cp_commit();

    for (int kt = 0; kt < 32; ++kt) {
        cp_wait<1>();
        __syncthreads();
        const uint32_t stg = sb + ATT_STG + (kt & 1) * ATT_STAGE;

        float acc[8][4];
        #pragma unroll
        for (int j = 0; j < 8; ++j)
            #pragma unroll
            for (int x = 0; x < 4; ++x) acc[j][x] = 0.f;
        computeS(stg, acc);

        #pragma unroll
        for (int kc = 0; kc < 4; ++kc) {
            const int j0 = kc * 2, j1 = j0 + 1;
            uint32_t aph[4];
            aph[0] = ex2_h2(acc[j0][0], acc[j0][1]);
            aph[1] = ex2_h2(acc[j0][2], acc[j0][3]);
            aph[2] = ex2_h2(acc[j1][0], acc[j1][1]);
            aph[3] = ex2_h2(acc[j1][2], acc[j1][3]);

            mma_f16(lacc, aph, ONESH2, ONESH2);   // l += row sums of e

            #pragma unroll
            for (int dkt = 0; dkt < 4; ++dkt) {
                const uint32_t off = (kc * 16 + (lane & 15)) * 144 + dkt * 32
                                   + (lane >> 4) * 16;
                uint32_t vh[4];
                ldsm_x4_t(vh, stg + ATT_VOF + off);
                mma_f16(ctx[dkt * 2],     aph, vh[0], vh[1]);
                mma_f16(ctx[dkt * 2 + 1], aph, vh[2], vh[3]);
            }
        }

        __syncthreads();
        if (kt + 2 < 32) loadKV(kt + 2, kt & 1);
        cp_commit();
    }

    // all columns of the l-mma are identical: no reduction needed
    const float l0 = lacc[0], l1 = lacc[2];
    const float rlog0 = -lg2(l0), rlog1 = -lg2(l1);
    const float rinv0 = 1.0f / l0, rinv1 = 1.0f / l1;

    // ====== PASS 2: column sums with final normalizer =====================
    loadK(0, 0); cp_commit();
    loadK(1, 1); cp_commit();

    for (int kt = 0; kt < 32; ++kt) {
        cp_wait<1>();
        __syncthreads();
        const uint32_t stg = sb + ATT_STG + (kt & 1) * ATT_STAGE;

        float acc[8][4];
        #pragma unroll
        for (int j = 0; j < 8; ++j)
            #pragma unroll
            for (int x = 0; x < 4; ++x) acc[j][x] = 0.f;
        computeS(stg, acc);

        float* amrow = &attn_mean[b * NSEQ + kt * 64];
        #pragma unroll
        for (int j = 0; j < 8; ++j) {
            uint32_t e01 = ex2_h2(acc[j][0] + rlog0, acc[j][1] + rlog0);
            uint32_t e23 = ex2_h2(acc[j][2] + rlog1, acc[j][3] + rlog1);
            float2 f01 = __half22float2(*(__half2*)&e01);
            float2 f23 = __half22float2(*(__half2*)&e23);
            float c0 = f01.x + f23.x, c1 = f01.y + f23.y;
            c0 += __shfl_xor_sync(0xffffffffu, c0, 4);
            c0 += __shfl_xor_sync(0xffffffffu, c0, 8);
            c0 += __shfl_xor_sync(0xffffffffu, c0, 16);
            c1 += __shfl_xor_sync(0xffffffffu, c1, 4);
            c1 += __shfl_xor_sync(0xffffffffu, c1, 8);
            c1 += __shfl_xor_sync(0xffffffffu, c1, 16);
            if (lane < 4) {
                atomicAdd(&amrow[j * 8 + lane * 2],     c0 * MSCALE);
                atomicAdd(&amrow[j * 8 + lane * 2 + 1], c1 * MSCALE);
            }
        }

        __syncthreads();
        if (kt + 2 < 32) loadK(kt + 2, kt & 1);
        cp_commit();
    }

    // epilogue: normalize ctx, hi-only fp16 store (B, N, H*dk layout)
    const int r0 = q0 + wid * 16 + g;
    #pragma unroll
    for (int nd = 0; nd < 8; ++nd) {
        const int col = h * 64 + nd * 8 + tg * 2;
        size_t i0 = ((size_t)(b * NSEQ + r0)) * DMODEL + col;
        *(uint32_t*)(g_ctxhi + i0) =
            pack_h2(ctx[nd][0] * rinv0, ctx[nd][1] * rinv0);
        *(uint32_t*)(g_ctxhi + i0 + 8 * DMODEL) =
            pack_h2(ctx[nd][2] * rinv1, ctx[nd][3] * rinv1);
    }
}

// ---------------------------------------------------------------------------
extern "C" void kernel_launch(void* const* d_in, const int* in_sizes, int n_in,
                              void* d_out, int out_size)
{
    const float* x     = (const float*)d_in[0];
    const float* w_qkv = (const float*)d_in[1];
    const float* b_qkv = (const float*)d_in[2];
    const float* w_out = (const float*)d_in[3];
    const float* b_out = (const float*)d_in[4];
    float* out = (float*)d_out;

    __half *qh, *xhi, *ctxhi, *wqh, *woh;
    cudaGetSymbolAddress((void**)&qh, g_qkvhi);
    cudaGetSymbolAddress((void**)&xhi, g_xhi);
    cudaGetSymbolAddress((void**)&ctxhi, g_ctxhi);
    cudaGetSymbolAddress((void**)&wqh, g_wqkvT_h);
    cudaGetSymbolAddress((void**)&woh, g_woutT_h);

    const int M = BDIM * NSEQ;                    // 4096
    float* attn_mean = out + (size_t)M * DMODEL;  // second output region

    cudaMemsetAsync(attn_mean, 0, (size_t)BDIM * NSEQ * sizeof(float));

    // prep: cast input, cast+transpose weights
    cast_h_kernel<<<1024, 256>>>(x, xhi, M * DMODEL / 4);
    transpose_h_kernel<<<dim3(TD / 32, DMODEL / 32), dim3(32, 8)>>>(
        w_qkv, wqh, DMODEL, TD);
    transpose_h_kernel<<<dim3(DMODEL / 32, DMODEL / 32), dim3(32, 8)>>>(
        w_out, woh, DMODEL, DMODEL);

    cudaFuncSetAttribute(gemm_mma_kernel,
                         cudaFuncAttributeMaxDynamicSharedMemorySize,
                         (int)GEMM_SMEM);
    cudaFuncSetAttribute(attn_mma_kernel,
                         cudaFuncAttributeMaxDynamicSharedMemorySize,
                         ATT_SMEM);

    // QKV projection (hi-only) -> fp16 output, Q pre-scaled
    gemm_mma_kernel<<<dim3(TD / 128, M / 128), 256, GEMM_SMEM>>>(
        xhi, wqh, b_qkv, nullptr, qh, M, TD, DMODEL);

    // attention (single-compute + colsum pass)
    attn_mma_kernel<<<dim3(NSEQ / 128, NHEADS * BDIM), 256, ATT_SMEM>>>(attn_mean);

    // output projection (hi-only) -> fp32 final output
    gemm_mma_kernel<<<dim3(DMODEL / 128, M / 128), 256, GEMM_SMEM>>>(
        ctxhi, woh, b_out, out, nullptr, M, DMODEL, DMODEL);
}

// round 17
// speedup vs baseline: 1.4145x; 1.0491x over previous
#include <cuda_runtime.h>
#include <cuda_fp16.h>
#include <cstdint>

#define BDIM   2
#define NSEQ   2048
#define DMODEL 1024
#define NHEADS 16
#define DKH    64
#define TD     3072   // 3*DMODEL

// ---------------------------------------------------------------------------
// Scratch (static device globals: allocation-free rule)
// ---------------------------------------------------------------------------
__device__ __half g_qkvhi[(size_t)BDIM * NSEQ * TD];
__device__ __half g_xhi[(size_t)BDIM * NSEQ * DMODEL];
__device__ __half g_ctxhi[(size_t)BDIM * NSEQ * DMODEL];
__device__ __half g_wqkvT_h[(size_t)TD * DMODEL];   // [N=3072][K=1024]
__device__ __half g_woutT_h[(size_t)DMODEL * DMODEL];

// ---------------------------------------------------------------------------
// PTX helpers (baseline ISA only: compiles under compute_103)
// ---------------------------------------------------------------------------
__device__ __forceinline__ uint32_t smem_to_u32(const void* p) {
    uint32_t a;
    asm("{ .reg .u64 t; cvta.to.shared.u64 t, %1; cvt.u32.u64 %0, t; }"
        : "=r"(a) : "l"(p));
    return a;
}
__device__ __forceinline__ void cp16(uint32_t s, const void* g) {
    asm volatile("cp.async.ca.shared.global [%0], [%1], 16;" :: "r"(s), "l"(g));
}
__device__ __forceinline__ void cp_commit() {
    asm volatile("cp.async.commit_group;");
}
template <int N> __device__ __forceinline__ void cp_wait() {
    asm volatile("cp.async.wait_group %0;" :: "n"(N));
}
__device__ __forceinline__ void ldsm_x4(uint32_t* r, uint32_t addr) {
    asm volatile("ldmatrix.sync.aligned.m8n8.x4.shared.b16 {%0,%1,%2,%3}, [%4];"
        : "=r"(r[0]), "=r"(r[1]), "=r"(r[2]), "=r"(r[3]) : "r"(addr));
}
__device__ __forceinline__ void ldsm_x4_t(uint32_t* r, uint32_t addr) {
    asm volatile("ldmatrix.sync.aligned.m8n8.x4.trans.shared.b16 {%0,%1,%2,%3}, [%4];"
        : "=r"(r[0]), "=r"(r[1]), "=r"(r[2]), "=r"(r[3]) : "r"(addr));
}
__device__ __forceinline__ void mma_f16(float* d, const uint32_t* a,
                                        uint32_t b0, uint32_t b1) {
    asm volatile(
        "mma.sync.aligned.m16n8k16.row.col.f32.f16.f16.f32 "
        "{%0,%1,%2,%3}, {%4,%5,%6,%7}, {%8,%9}, {%0,%1,%2,%3};"
        : "+f"(d[0]), "+f"(d[1]), "+f"(d[2]), "+f"(d[3])
        : "r"(a[0]), "r"(a[1]), "r"(a[2]), "r"(a[3]), "r"(b0), "r"(b1));
}
__device__ __forceinline__ uint32_t movm(uint32_t x) {
    uint32_t y;
    asm("movmatrix.sync.aligned.m8n8.trans.b16 %0, %1;" : "=r"(y) : "r"(x));
    return y;
}
__device__ __forceinline__ float lg2(float x) {
    float y; asm("lg2.approx.f32 %0, %1;" : "=f"(y) : "f"(x)); return y;
}
// pack (lo, hi) floats into one f16x2 register (lo -> low half)
__device__ __forceinline__ uint32_t pack_h2(float lo, float hi) {
    uint32_t p;
    asm("cvt.rn.f16x2.f32 %0, %1, %2;" : "=r"(p) : "f"(hi), "f"(lo));
    return p;
}
// vectorized exp2: returns f16x2{exp2(lo), exp2(hi)}
__device__ __forceinline__ uint32_t ex2_h2(float lo, float hi) {
    uint32_t p, r;
    asm("cvt.rn.f16x2.f32 %0, %1, %2;" : "=r"(p) : "f"(hi), "f"(lo));
    asm("ex2.approx.f16x2 %0, %1;" : "=r"(r) : "r"(p));
    return r;
}

// ---------------------------------------------------------------------------
// Cast fp32 -> fp16, elementwise (vectorized)
// ---------------------------------------------------------------------------
__global__ __launch_bounds__(256) void cast_h_kernel(
    const float* __restrict__ src, __half* __restrict__ dst, int n4)
{
    for (int i = blockIdx.x * blockDim.x + threadIdx.x; i < n4;
         i += gridDim.x * blockDim.x) {
        float4 v = ((const float4*)src)[i];
        uint2 o;
        o.x = pack_h2(v.x, v.y);
        o.y = pack_h2(v.z, v.w);
        ((uint2*)dst)[i] = o;
    }
}

// ---------------------------------------------------------------------------
// Transpose + fp16 cast: src [K][N] fp32 -> hiT [N][K] fp16
// ---------------------------------------------------------------------------
__global__ __launch_bounds__(256) void transpose_h_kernel(
    const float* __restrict__ src, __half* __restrict__ hiT, int K, int N)
{
    __shared__ float tile[32][33];
    const int tx = threadIdx.x, ty = threadIdx.y;   // (32, 8)
    const int n0 = blockIdx.x * 32, k0 = blockIdx.y * 32;

    #pragma unroll
    for (int i = 0; i < 4; ++i)
        tile[ty + i * 8][tx] = src[(size_t)(k0 + ty + i * 8) * N + n0 + tx];
    __syncthreads();

    #pragma unroll
    for (int i = 0; i < 4; ++i) {
        int n = n0 + ty + i * 8;
        hiT[(size_t)n * K + k0 + tx] = __float2half_rn(tile[tx][ty + i * 8]);
    }
}

// ---------------------------------------------------------------------------
// fp16 hi-only GEMM, BK=64 (half the barriers), double-sync 2-stage cp.async.
// C = A @ B + bias; A fp16 [M][K]; B fp16 transposed [Nc][K].
// Output: fp32 C, or fp16 Chi with Q pre-scale (col%192 < 64 by 0.125*log2e).
// CTA 128x128, 256 threads, warp tile 32x64, 144B-padded rows.
// ---------------------------------------------------------------------------
#define A_OFF 0
#define B_OFF 18432
#define STAGE_SZ 36864
static constexpr size_t GEMM_SMEM = 2 * STAGE_SZ;  // 73728

__global__ __launch_bounds__(256, 2) void gemm_mma_kernel(
    const __half* __restrict__ Ahi, const __half* __restrict__ BTh,
    const float* __restrict__ bias, float* __restrict__ C,
    __half* __restrict__ Chi,
    int M, int Nc, int K)
{
    extern __shared__ char smc[];
    const uint32_t sbase = smem_to_u32(smc);
    const int tid = threadIdx.x;
    const int lane = tid & 31, wid = tid >> 5;
    const int wm = (wid & 3) * 32;
    const int wn = (wid >> 2) * 64;
    const int bm = blockIdx.y * 128, bn = blockIdx.x * 128;

    const int lrow = tid >> 1;          // 0..127
    const int lc   = tid & 1;           // half-row selector

    const __half* gAh = Ahi + (size_t)(bm + lrow) * K + lc * 32;
    const __half* gBh = BTh + (size_t)(bn + lrow) * K + lc * 32;
    const uint32_t sRow = lrow * 144 + lc * 64;

    auto load_stage = [&](int k0, int buf) {
        uint32_t st = sbase + buf * STAGE_SZ;
        #pragma unroll
        for (int c = 0; c < 4; ++c) {
            cp16(st + A_OFF + sRow + c * 16, gAh + k0 + c * 8);
            cp16(st + B_OFF + sRow + c * 16, gBh + k0 + c * 8);
        }
    };

    float acc[2][8][4];
    #pragma unroll
    for (int a = 0; a < 2; ++a)
        #pragma unroll
        for (int b = 0; b < 8; ++b)
            #pragma unroll
            for (int c = 0; c < 4; ++c) acc[a][b][c] = 0.f;

    const int arow = wm + (lane & 15);
    const int brow = wn + (lane & 15);
    const int klb  = (lane >> 4) * 16;

    const int nit = K / 64;
    load_stage(0, 0);
    cp_commit();

    for (int i = 0; i < nit; ++i) {
        const int cur = i & 1;
        if (i + 1 < nit) { load_stage((i + 1) * 64, cur ^ 1); cp_commit(); }
        if (i + 1 < nit) cp_wait<1>(); else cp_wait<0>();
        __syncthreads();

        const uint32_t st = sbase + cur * STAGE_SZ;
        #pragma unroll
        for (int ks = 0; ks < 4; ++ks) {
            const uint32_t kb = ks * 32 + klb;
            uint32_t ah[2][4], bh[4][4];
            #pragma unroll
            for (int mt = 0; mt < 2; ++mt)
                ldsm_x4(ah[mt], st + A_OFF + (arow + mt * 16) * 144 + kb);
            #pragma unroll
            for (int nt = 0; nt < 4; ++nt)
                ldsm_x4(bh[nt], st + B_OFF + (brow + nt * 16) * 144 + kb);

            #pragma unroll
            for (int mt = 0; mt < 2; ++mt)
                #pragma unroll
                for (int j = 0; j < 8; ++j)
                    mma_f16(acc[mt][j], ah[mt], bh[j >> 1][j & 1],
                            bh[j >> 1][(j & 1) + 2]);
        }
        __syncthreads();
    }

    // epilogue
    const int g = lane >> 2, tq = lane & 3;
    #pragma unroll
    for (int mt = 0; mt < 2; ++mt) {
        const int r0 = bm + wm + mt * 16 + g;
        #pragma unroll
        for (int j = 0; j < 8; ++j) {
            const int col = bn + wn + j * 8 + tq * 2;
            const float b0 = bias[col], b1 = bias[col + 1];
            float v00 = acc[mt][j][0] + b0, v01 = acc[mt][j][1] + b1;
            float v10 = acc[mt][j][2] + b0, v11 = acc[mt][j][3] + b1;
            if (C) {
                *(float2*)&C[(size_t)r0 * Nc + col] = make_float2(v00, v01);
                *(float2*)&C[(size_t)(r0 + 8) * Nc + col] = make_float2(v10, v11);
            } else {
                // QKV path: pre-scale Q columns by 0.125*log2(e)
                const float s = ((col % 192) < 64) ? 0.18033688f : 1.0f;
                *(uint32_t*)(Chi + (size_t)r0 * Nc + col) =
                    pack_h2(v00 * s, v01 * s);
                *(uint32_t*)(Chi + (size_t)(r0 + 8) * Nc + col) =
                    pack_h2(v10 * s, v11 * s);
            }
        }
    }
}

// ---------------------------------------------------------------------------
// MMA attention (Q pre-scaled so S is in log2 units):
// Pass 1: S = QK (hi), e = ex2.f16x2(S) directly as PV a-fragments,
//         l via ones-column mma, ctxU += e*V.
// Pass 2: recompute S (hi), f16x2 exp with final normalizer, colsums via
//         movmatrix + ones-mma (contraction over q), direct atomics.
// Epilogue: ctx = ctxU / l, hi-only fp16 store.
// ---------------------------------------------------------------------------
#define ATT_QHI   0
#define ATT_STG   18432
#define ATT_STAGE 18432
#define ATT_VOF   9216
#define ATT_SMEM  55296

__global__ __launch_bounds__(256, 2) void attn_mma_kernel(float* __restrict__ attn_mean)
{
    extern __shared__ char smc[];
    const uint32_t sb = smem_to_u32(smc);
    const int tid = threadIdx.x, lane = tid & 31, wid = tid >> 5;
    const int g = lane >> 2, tg = lane & 3;
    const int h = blockIdx.y >> 1, b = blockIdx.y & 1;
    const int q0 = blockIdx.x * 128;
    const float MSCALE = 1.0f / (NHEADS * (float)NSEQ);
    const uint32_t ONESH2 = 0x3C003C00u;   // f16x2 {1.0, 1.0}
    const uint32_t onesA[4] = {ONESH2, ONESH2, ONESH2, ONESH2};

    const int lr = tid >> 3, lch = tid & 7;
    const size_t rowQ  = ((size_t)(b * NSEQ + q0 + lr)) * TD + h * 192 + lch * 8;
    const size_t rowKV = ((size_t)(b * NSEQ + lr)) * TD + h * 192 + lch * 8;
    const uint32_t soff = lr * 144 + lch * 16;
    const size_t KTSTEP = (size_t)64 * TD;

    auto loadQ = [&]() {
        #pragma unroll
        for (int i = 0; i < 4; ++i)
            cp16(sb + ATT_QHI + soff + i * 32 * 144,
                 g_qkvhi + rowQ + (size_t)i * 32 * TD);
    };
    auto loadK = [&](int kt, int s) {
        uint32_t st = sb + ATT_STG + s * ATT_STAGE;
        size_t base = rowKV + (size_t)kt * KTSTEP + 64;
        cp16(st + soff,            g_qkvhi + base);
        cp16(st + soff + 32 * 144, g_qkvhi + base + 32 * TD);
    };
    auto loadKV = [&](int kt, int s) {
        uint32_t st = sb + ATT_STG + s * ATT_STAGE;
        size_t base = rowKV + (size_t)kt * KTSTEP + 64;
        cp16(st + soff,            g_qkvhi + base);
        cp16(st + soff + 32 * 144, g_qkvhi + base + 32 * TD);
        cp16(st + ATT_VOF + soff,            g_qkvhi + base + 64);
        cp16(st + ATT_VOF + soff + 32 * 144, g_qkvhi + base + 64 + 32 * TD);
    };

    const uint32_t klb  = (lane >> 4) * 16;
    const uint32_t arow = wid * 16 + (lane & 15);
    const uint32_t brow = lane & 15;

    auto computeS = [&](uint32_t stg, float (*acc)[4]) {
        #pragma unroll
        for (int ks = 0; ks < 4; ++ks) {
            const uint32_t kb = ks * 32 + klb;
            uint32_t ah[4], bh[4][4];
            ldsm_x4(ah, sb + ATT_QHI + arow * 144 + kb);
            #pragma unroll
            for (int nt = 0; nt < 4; ++nt)
                ldsm_x4(bh[nt], stg + (brow + nt * 16) * 144 + kb);
            #pragma unroll
            for (int nt = 0; nt < 4; ++nt)
                #pragma unroll
                for (int o = 0; o < 2; ++o)
                    mma_f16(acc[nt * 2 + o], ah, bh[nt][o], bh[nt][o + 2]);
        }
    };

    float lacc[4] = {0.f, 0.f, 0.f, 0.f};
    float ctx[8][4];
    #pragma unroll
    for (int j = 0; j < 8; ++j)
        #pragma unroll
        for (int x = 0; x < 4; ++x) ctx[j][x] = 0.f;

    // ====== PASS 1: e = ex2(S) f16x2, l via ones-mma, ctxU += e*V =========
    loadQ(); loadKV(0, 0); cp_commit();
    loadKV(1, 1); cp_commit();

    for (int kt = 0; kt < 32; ++kt) {
        cp_wait<1>();
        __syncthreads();
        const uint32_t stg = sb + ATT_STG + (kt & 1) * ATT_STAGE;

        float acc[8][4];
        #pragma unroll
        for (int j = 0; j < 8; ++j)
            #pragma unroll
            for (int x = 0; x < 4; ++x) acc[j][x] = 0.f;
        computeS(stg, acc);

        #pragma unroll
        for (int kc = 0; kc < 4; ++kc) {
            const int j0 = kc * 2, j1 = j0 + 1;
            uint32_t aph[4];
            aph[0] = ex2_h2(acc[j0][0], acc[j0][1]);
            aph[1] = ex2_h2(acc[j0][2], acc[j0][3]);
            aph[2] = ex2_h2(acc[j1][0], acc[j1][1]);
            aph[3] = ex2_h2(acc[j1][2], acc[j1][3]);

            mma_f16(lacc, aph, ONESH2, ONESH2);   // l += row sums of e

            #pragma unroll
            for (int dkt = 0; dkt < 4; ++dkt) {
                const uint32_t off = (kc * 16 + (lane & 15)) * 144 + dkt * 32
                                   + (lane >> 4) * 16;
                uint32_t vh[4];
                ldsm_x4_t(vh, stg + ATT_VOF + off);
                mma_f16(ctx[dkt * 2],     aph, vh[0], vh[1]);
                mma_f16(ctx[dkt * 2 + 1], aph, vh[2], vh[3]);
            }
        }

        __syncthreads();
        if (kt + 2 < 32) loadKV(kt + 2, kt & 1);
        cp_commit();
    }

    // all columns of the l-mma are identical: no reduction needed
    const float l0 = lacc[0], l1 = lacc[2];
    const float rlog0 = -lg2(l0), rlog1 = -lg2(l1);
    const float rinv0 = 1.0f / l0, rinv1 = 1.0f / l1;

    // ====== PASS 2: colsums via movmatrix + ones-mma ======================
    loadK(0, 0); cp_commit();
    loadK(1, 1); cp_commit();

    for (int kt = 0; kt < 32; ++kt) {
        cp_wait<1>();
        __syncthreads();
        const uint32_t stg = sb + ATT_STG + (kt & 1) * ATT_STAGE;

        float acc[8][4];
        #pragma unroll
        for (int j = 0; j < 8; ++j)
            #pragma unroll
            for (int x = 0; x < 4; ++x) acc[j][x] = 0.f;
        computeS(stg, acc);

        float* amrow = &attn_mean[b * NSEQ + kt * 64];
        #pragma unroll
        for (int kc = 0; kc < 4; ++kc) {
            const int j0 = kc * 2, j1 = j0 + 1;
            uint32_t aph[4];
            aph[0] = ex2_h2(acc[j0][0] + rlog0, acc[j0][1] + rlog0);
            aph[1] = ex2_h2(acc[j0][2] + rlog1, acc[j0][3] + rlog1);
            aph[2] = ex2_h2(acc[j1][0] + rlog0, acc[j1][1] + rlog0);
            aph[3] = ex2_h2(acc[j1][2] + rlog1, acc[j1][3] + rlog1);

            // transpose e fragments -> b operands of E (contraction over q)
            uint32_t t0 = movm(aph[0]), t1 = movm(aph[1]);
            uint32_t t2 = movm(aph[2]), t3 = movm(aph[3]);

            float colA[4] = {0.f, 0.f, 0.f, 0.f};
            float colB[4] = {0.f, 0.f, 0.f, 0.f};
            mma_f16(colA, onesA, t0, t1);   // keys kc*16 + 0..7
            mma_f16(colB, onesA, t2, t3);   // keys kc*16 + 8..15
            if (lane < 4) {
                atomicAdd(&amrow[kc * 16 + lane * 2],     colA[0] * MSCALE);
                atomicAdd(&amrow[kc * 16 + lane * 2 + 1], colA[1] * MSCALE);
                atomicAdd(&amrow[kc * 16 + 8 + lane * 2],     colB[0] * MSCALE);
                atomicAdd(&amrow[kc * 16 + 8 + lane * 2 + 1], colB[1] * MSCALE);
            }
        }

        __syncthreads();
        if (kt + 2 < 32) loadK(kt + 2, kt & 1);
        cp_commit();
    }

    // epilogue: normalize ctx, hi-only fp16 store (B, N, H*dk layout)
    const int r0 = q0 + wid * 16 + g;
    #pragma unroll
    for (int nd = 0; nd < 8; ++nd) {
        const int col = h * 64 + nd * 8 + tg * 2;
        size_t i0 = ((size_t)(b * NSEQ + r0)) * DMODEL + col;
        *(uint32_t*)(g_ctxhi + i0) =
            pack_h2(ctx[nd][0] * rinv0, ctx[nd][1] * rinv0);
        *(uint32_t*)(g_ctxhi + i0 + 8 * DMODEL) =
            pack_h2(ctx[nd][2] * rinv1, ctx[nd][3] * rinv1);
    }
}

// ---------------------------------------------------------------------------
extern "C" void kernel_launch(void* const* d_in, const int* in_sizes, int n_in,
                              void* d_out, int out_size)
{
    const float* x     = (const float*)d_in[0];
    const float* w_qkv = (const float*)d_in[1];
    const float* b_qkv = (const float*)d_in[2];
    const float* w_out = (const float*)d_in[3];
    const float* b_out = (const float*)d_in[4];
    float* out = (float*)d_out;

    __half *qh, *xhi, *ctxhi, *wqh, *woh;
    cudaGetSymbolAddress((void**)&qh, g_qkvhi);
    cudaGetSymbolAddress((void**)&xhi, g_xhi);
    cudaGetSymbolAddress((void**)&ctxhi, g_ctxhi);
    cudaGetSymbolAddress((void**)&wqh, g_wqkvT_h);
    cudaGetSymbolAddress((void**)&woh, g_woutT_h);

    const int M = BDIM * NSEQ;                    // 4096
    float* attn_mean = out + (size_t)M * DMODEL;  // second output region

    cudaMemsetAsync(attn_mean, 0, (size_t)BDIM * NSEQ * sizeof(float));

    // prep: cast input, cast+transpose weights
    cast_h_kernel<<<1024, 256>>>(x, xhi, M * DMODEL / 4);
    transpose_h_kernel<<<dim3(TD / 32, DMODEL / 32), dim3(32, 8)>>>(
        w_qkv, wqh, DMODEL, TD);
    transpose_h_kernel<<<dim3(DMODEL / 32, DMODEL / 32), dim3(32, 8)>>>(
        w_out, woh, DMODEL, DMODEL);

    cudaFuncSetAttribute(gemm_mma_kernel,
                         cudaFuncAttributeMaxDynamicSharedMemorySize,
                         (int)GEMM_SMEM);
    cudaFuncSetAttribute(attn_mma_kernel,
                         cudaFuncAttributeMaxDynamicSharedMemorySize,
                         ATT_SMEM);

    // QKV projection (hi-only) -> fp16 output, Q pre-scaled
    gemm_mma_kernel<<<dim3(TD / 128, M / 128), 256, GEMM_SMEM>>>(
        xhi, wqh, b_qkv, nullptr, qh, M, TD, DMODEL);

    // attention (single-compute + colsum pass)
    attn_mma_kernel<<<dim3(NSEQ / 128, NHEADS * BDIM), 256, ATT_SMEM>>>(attn_mean);

    // output projection (hi-only) -> fp32 final output
    gemm_mma_kernel<<<dim3(DMODEL / 128, M / 128), 256, GEMM_SMEM>>>(
        ctxhi, woh, b_out, out, nullptr, M, DMODEL, DMODEL);
}